// round 2
// baseline (speedup 1.0000x reference)
#include <cuda_runtime.h>
#include <cuda_bf16.h>

#define W_IMG 640
#define H_IMG 480
#define HW_IMG (W_IMG * H_IMG)
#define NSWEEPS 6

// Scratch (no allocations allowed): projection matrices + per-pixel winner index.
__device__ float g_P[24];          // P0 (3x4) then P1 (3x4), row-major
__device__ int   g_winner[HW_IMG]; // last-write-wins replication: max point index per pixel

// rsqrt on the FMA/ALU pipes (avoid MUFU — it would be a throughput bottleneck
// at ~2 uses x 36 rotations x 1M threads). Magic seed + 2 Newton steps: ~1e-7 rel err.
__device__ __forceinline__ float frsqrt_nr(float z) {
    float y = __int_as_float(0x5f3759df - (__float_as_int(z) >> 1));
    y = y * fmaf(-0.5f * z * y, y, 1.5f);
    y = y * fmaf(-0.5f * z * y, y, 1.5f);
    return y;
}

// Resets the winner map every launch (graph replays!) and computes P0/P1 once.
__global__ void prep_kernel(const float* __restrict__ T,
                            const float* __restrict__ K0,
                            const float* __restrict__ K1) {
    int i = blockIdx.x * blockDim.x + threadIdx.x;
    if (i < HW_IMG) g_winner[i] = -1;
    if (i == 0) {
        // P0 = K0 @ [I|0]
        for (int r = 0; r < 3; r++)
            for (int c = 0; c < 4; c++)
                g_P[r * 4 + c] = (c < 3) ? K0[r * 3 + c] : 0.0f;
        // P1 = K1 @ T[:3,:]
        for (int r = 0; r < 3; r++)
            for (int c = 0; c < 4; c++) {
                float acc = 0.0f;
                for (int k = 0; k < 3; k++) acc += K1[r * 3 + k] * T[k * 4 + c];
                g_P[12 + r * 4 + c] = acc;
            }
    }
}

__global__ void __launch_bounds__(256)
tri_kernel(const float* __restrict__ mconf,
           const float* __restrict__ kp0,
           const float* __restrict__ kp1,
           float* __restrict__ out, int N) {
    int n = blockIdx.x * blockDim.x + threadIdx.x;
    if (n >= N) return;

    float2 p0 = reinterpret_cast<const float2*>(kp0)[n];
    float2 p1 = reinterpret_cast<const float2*>(kp1)[n];
    float  cf = mconf[n];

    float P[24];
#pragma unroll
    for (int i = 0; i < 24; i++) P[i] = g_P[i];  // warp-uniform, L1 broadcast

    // A rows: (x0*P0r2 - P0r0), (y0*P0r2 - P0r1), cf*(x1*P1r2 - P1r0), cf*(y1*P1r2 - P1r1)
    float A[4][4];
#pragma unroll
    for (int j = 0; j < 4; j++) {
        A[0][j] = fmaf(p0.x, P[8 + j],  -P[0 + j]);
        A[1][j] = fmaf(p0.y, P[8 + j],  -P[4 + j]);
        A[2][j] = cf * fmaf(p1.x, P[20 + j], -P[12 + j]);
        A[3][j] = cf * fmaf(p1.y, P[20 + j], -P[16 + j]);
    }

    // Right-singular-vector accumulator: rotations mix V COLUMNS within each
    // row independently, and we only ever read rows 2 and 3 (the z and w
    // components). So track just those two rows.
    float V2[4] = {0.f, 0.f, 1.f, 0.f};
    float V3[4] = {0.f, 0.f, 0.f, 1.f};

    // One-sided cyclic Jacobi SVD: orthogonalize column pairs of A.
    const int PP[6] = {0, 0, 0, 1, 1, 2};
    const int QQ[6] = {1, 2, 3, 2, 3, 3};
#pragma unroll 1
    for (int sw = 0; sw < NSWEEPS; sw++) {
#pragma unroll
        for (int pi = 0; pi < 6; pi++) {
            const int p = PP[pi], q = QQ[pi];
            float al = 0.0f, be = 0.0f, ga = 0.0f;
#pragma unroll
            for (int k = 0; k < 4; k++) {
                al = fmaf(A[k][p], A[k][p], al);
                be = fmaf(A[k][q], A[k][q], be);
                ga = fmaf(A[k][p], A[k][q], ga);
            }
            // Rotation zeroing the Gram off-diagonal:
            //   u = be-al, w = 2*ga, (c,s) ∝ (|u| + sqrt(u^2+w^2), w*sgn(u))
            // (identity: cs(al-be) + (c^2-s^2)ga == 0). sqrt on FMA pipe.
            float u  = be - al;
            float w  = ga + ga;
            float zz = fmaf(u, u, w * w);
            float h  = zz * frsqrt_nr(zz);                 // sqrt(u^2+w^2); 0 if zz==0
            float d  = fabsf(u) + h;
            float sr = w * copysignf(1.0f, u);
            float rn = frsqrt_nr(fmaf(d, d, sr * sr));
            bool  ok = d > 0.0f;                            // exactly-degenerate guard
            float c  = ok ? d * rn  : 1.0f;
            float s  = ok ? sr * rn : 0.0f;
#pragma unroll
            for (int k = 0; k < 4; k++) {
                float ap = A[k][p], aq = A[k][q];
                A[k][p] = fmaf(c, ap, -s * aq);
                A[k][q] = fmaf(s, ap,  c * aq);
            }
            { float vp = V2[p], vq = V2[q];
              V2[p] = fmaf(c, vp, -s * vq);
              V2[q] = fmaf(s, vp,  c * vq); }
            { float vp = V3[p], vq = V3[q];
              V3[p] = fmaf(c, vp, -s * vq);
              V3[q] = fmaf(s, vp,  c * vq); }
        }
    }

    // Column with smallest norm == smallest right singular vector.
    float best = 3.4e38f, v2 = 0.f, v3 = 1.f;
#pragma unroll
    for (int j = 0; j < 4; j++) {
        float t = 0.0f;
#pragma unroll
        for (int k = 0; k < 4; k++) t = fmaf(A[k][j], A[k][j], t);
        if (t < best) { best = t; v2 = V2[j]; v3 = V3[j]; }
    }

    // Sign of v cancels in the division. Clip(+-1000), clip(0,30), strict filter.
    float zraw = v2 / v3;
    float pc   = fminf(fmaxf(zraw, -1000.0f), 1000.0f);
    float zc   = fminf(fmaxf(pc, 0.0f), 30.0f);
    float val  = (zc > 0.0f && zc < 30.0f) ? zc : 0.0f;

    out[HW_IMG + n] = val;

    // Sparse-depth scatter, last-write-wins: highest point index owns the pixel.
    int xi = (int)p0.x;   // trunc toward zero == .astype(int32) for x>=0
    int yi = (int)p0.y;
    atomicMax(&g_winner[yi * W_IMG + xi], n);
}

__global__ void resolve_kernel(float* __restrict__ out) {
    int i = blockIdx.x * blockDim.x + threadIdx.x;
    if (i < HW_IMG) {
        int wn = g_winner[i];
        out[i] = (wn >= 0) ? out[HW_IMG + wn] : 0.0f;
    }
}

extern "C" void kernel_launch(void* const* d_in, const int* in_sizes, int n_in,
                              void* d_out, int out_size) {
    const float* T     = (const float*)d_in[0];  // [1,4,4]
    const float* K0    = (const float*)d_in[1];  // [1,3,3]
    const float* K1    = (const float*)d_in[2];  // [1,3,3]
    const float* mconf = (const float*)d_in[3];  // [N]
    const float* kp0   = (const float*)d_in[4];  // [N,2]
    const float* kp1   = (const float*)d_in[5];  // [N,2]
    // d_in[6] = image0 (fixed 480x640), d_in[7] = m_bids (all zero, single batch)
    int N = in_sizes[3];
    float* out = (float*)d_out;  // [HW_IMG depth | N kp3d_val]

    prep_kernel<<<(HW_IMG + 255) / 256, 256>>>(T, K0, K1);
    tri_kernel<<<(N + 255) / 256, 256>>>(mconf, kp0, kp1, out, N);
    resolve_kernel<<<(HW_IMG + 255) / 256, 256>>>(out);
}

// round 3
// speedup vs baseline: 1.2409x; 1.2409x over previous
#include <cuda_runtime.h>
#include <cuda_bf16.h>

#define W_IMG 640
#define H_IMG 480
#define HW_IMG (W_IMG * H_IMG)
#define NSWEEPS 5

// Per-pixel winner (last-write-wins replication of .at[].set with duplicates).
// Sentinel 0 = empty; stores n+1. Zero-initialized at module load; resolve_kernel
// restores zeros after reading, so the invariant holds across graph replays.
__device__ int g_winner[HW_IMG];

// MUFU.RSQ — offload rsqrt from the (bottleneck) FMA pipe to the idle MUFU pipe.
__device__ __forceinline__ float rsqrt_approx(float x) {
    float y;
    asm("rsqrt.approx.f32 %0, %1;" : "=f"(y) : "f"(x));
    return y;
}
// rcp.approx + 1 Newton: ~full fp32 precision, once per thread.
__device__ __forceinline__ float rcp_nr(float x) {
    float y;
    asm("rcp.approx.f32 %0, %1;" : "=f"(y) : "f"(x));
    return y * fmaf(-x, y, 2.0f);
}

__global__ void __launch_bounds__(256)
tri_kernel(const float* __restrict__ T,
           const float* __restrict__ K0,
           const float* __restrict__ K1,
           const float* __restrict__ mconf,
           const float* __restrict__ kp0,
           const float* __restrict__ kp1,
           float* __restrict__ out, int N) {
    int n = blockIdx.x * blockDim.x + threadIdx.x;
    if (n >= N) return;

    float2 p0 = reinterpret_cast<const float2*>(kp0)[n];
    float2 p1 = reinterpret_cast<const float2*>(kp1)[n];
    float  cf = mconf[n];

    // Projection matrices, computed per-thread (warp-uniform loads, L1 broadcast;
    // ~36 FMAs = 2% of thread work, cheaper than a dedicated prep launch).
    float P[24];
    // P0 = K0 @ [I|0]
#pragma unroll
    for (int r = 0; r < 3; r++) {
#pragma unroll
        for (int c = 0; c < 3; c++) P[r * 4 + c] = K0[r * 3 + c];
        P[r * 4 + 3] = 0.0f;
    }
    // P1 = K1 @ T[:3,:]
#pragma unroll
    for (int r = 0; r < 3; r++)
#pragma unroll
        for (int c = 0; c < 4; c++)
            P[12 + r * 4 + c] = fmaf(K1[r * 3 + 0], T[c],
                                fmaf(K1[r * 3 + 1], T[4 + c],
                                     K1[r * 3 + 2] * T[8 + c]));

    // A rows: (x0*P0r2 - P0r0), (y0*P0r2 - P0r1), cf*(x1*P1r2 - P1r0), cf*(y1*P1r2 - P1r1)
    float A[4][4];
#pragma unroll
    for (int j = 0; j < 4; j++) {
        A[0][j] = fmaf(p0.x, P[8 + j],  -P[0 + j]);
        A[1][j] = fmaf(p0.y, P[8 + j],  -P[4 + j]);
        A[2][j] = cf * fmaf(p1.x, P[20 + j], -P[12 + j]);
        A[3][j] = cf * fmaf(p1.y, P[20 + j], -P[16 + j]);
    }

    // Right-singular-vector accumulator: only rows 2 and 3 of V are ever read.
    float V2[4] = {0.f, 0.f, 1.f, 0.f};
    float V3[4] = {0.f, 0.f, 0.f, 1.f};

    // One-sided cyclic Jacobi SVD: orthogonalize column pairs of A.
    const int PP[6] = {0, 0, 0, 1, 1, 2};
    const int QQ[6] = {1, 2, 3, 2, 3, 3};
#pragma unroll 1
    for (int sw = 0; sw < NSWEEPS; sw++) {
#pragma unroll
        for (int pi = 0; pi < 6; pi++) {
            const int p = PP[pi], q = QQ[pi];
            float al = 0.0f, be = 0.0f, ga = 0.0f;
#pragma unroll
            for (int k = 0; k < 4; k++) {
                al = fmaf(A[k][p], A[k][p], al);
                be = fmaf(A[k][q], A[k][q], be);
                ga = fmaf(A[k][p], A[k][q], ga);
            }
            // Rotation zeroing the Gram off-diagonal:
            //   u = be-al, w = 2*ga, (c,s) ∝ (|u| + sqrt(u^2+w^2), w*sgn(u)).
            // Approx rsqrt keeps (c,s) an exact SCALED rotation: column pairs get a
            // common scale factor which cancels in the final v2/v3 ratio.
            float u  = be - al;
            float w  = ga + ga;
            float zz = fmaf(u, u, w * w);
            float h  = zz * rsqrt_approx(zz);               // sqrt(u^2+w^2) on MUFU
            float d  = fabsf(u) + h;
            float sr = w * copysignf(1.0f, u);
            float rn = rsqrt_approx(fmaf(d, d, sr * sr));   // MUFU
            bool  ok = zz > 0.0f;                           // degenerate pair guard
            float c  = ok ? d * rn  : 1.0f;
            float s  = ok ? sr * rn : 0.0f;
#pragma unroll
            for (int k = 0; k < 4; k++) {
                float ap = A[k][p], aq = A[k][q];
                A[k][p] = fmaf(c, ap, -s * aq);
                A[k][q] = fmaf(s, ap,  c * aq);
            }
            { float vp = V2[p], vq = V2[q];
              V2[p] = fmaf(c, vp, -s * vq);
              V2[q] = fmaf(s, vp,  c * vq); }
            { float vp = V3[p], vq = V3[q];
              V3[p] = fmaf(c, vp, -s * vq);
              V3[q] = fmaf(s, vp,  c * vq); }
        }
    }

    // Column with smallest norm == smallest right singular vector.
    float best = 3.4e38f, v2 = 0.f, v3 = 1.f;
#pragma unroll
    for (int j = 0; j < 4; j++) {
        float t = 0.0f;
#pragma unroll
        for (int k = 0; k < 4; k++) t = fmaf(A[k][j], A[k][j], t);
        if (t < best) { best = t; v2 = V2[j]; v3 = V3[j]; }
    }

    // Sign of v cancels in the division. Clip(+-1000), clip(0,30), strict filter.
    float zraw = v2 * rcp_nr(v3);
    float pc   = fminf(fmaxf(zraw, -1000.0f), 1000.0f);
    float zc   = fminf(fmaxf(pc, 0.0f), 30.0f);
    float val  = (zc > 0.0f && zc < 30.0f) ? zc : 0.0f;

    out[HW_IMG + n] = val;

    // Sparse-depth scatter, last-write-wins: highest point index owns the pixel.
    int xi = (int)p0.x;   // trunc toward zero == .astype(int32) for x>=0
    int yi = (int)p0.y;
    atomicMax(&g_winner[yi * W_IMG + xi], n + 1);
}

__global__ void resolve_kernel(float* __restrict__ out) {
    int i = blockIdx.x * blockDim.x + threadIdx.x;
    if (i < HW_IMG) {
        int wn = g_winner[i];
        out[i] = (wn > 0) ? out[HW_IMG + wn - 1] : 0.0f;
        g_winner[i] = 0;   // self-clean: restore the zero invariant for next call
    }
}

extern "C" void kernel_launch(void* const* d_in, const int* in_sizes, int n_in,
                              void* d_out, int out_size) {
    const float* T     = (const float*)d_in[0];  // [1,4,4]
    const float* K0    = (const float*)d_in[1];  // [1,3,3]
    const float* K1    = (const float*)d_in[2];  // [1,3,3]
    const float* mconf = (const float*)d_in[3];  // [N]
    const float* kp0   = (const float*)d_in[4];  // [N,2]
    const float* kp1   = (const float*)d_in[5];  // [N,2]
    // d_in[6] = image0 (fixed 480x640), d_in[7] = m_bids (all zero, single batch)
    int N = in_sizes[3];
    float* out = (float*)d_out;  // [HW_IMG depth | N kp3d_val]

    tri_kernel<<<(N + 255) / 256, 256>>>(T, K0, K1, mconf, kp0, kp1, out, N);
    resolve_kernel<<<(HW_IMG + 255) / 256, 256>>>(out);
}

// round 5
// speedup vs baseline: 1.4275x; 1.1504x over previous
#include <cuda_runtime.h>
#include <cuda_bf16.h>

#define W_IMG 640
#define H_IMG 480
#define HW_IMG (W_IMG * H_IMG)
#define NSWEEPS 4

// Per-pixel packed winner: high 32 bits = point index + 1 (last-write-wins key:
// largest index wins, replicating .at[].set with duplicates), low 32 bits =
// float bits of that point's depth value. 0 = empty. Zero-initialized at module
// load; resolve_kernel restores zeros after reading (invariant across replays).
__device__ unsigned long long g_pack[HW_IMG];

// MUFU.RSQ — offload rsqrt from the (bottleneck) FMA pipe to the idle MUFU pipe.
__device__ __forceinline__ float rsqrt_approx(float x) {
    float y;
    asm("rsqrt.approx.f32 %0, %1;" : "=f"(y) : "f"(x));
    return y;
}
// rcp.approx + 1 Newton: ~full fp32 precision, once per thread.
__device__ __forceinline__ float rcp_nr(float x) {
    float y;
    asm("rcp.approx.f32 %0, %1;" : "=f"(y) : "f"(x));
    return y * fmaf(-x, y, 2.0f);
}

__global__ void __launch_bounds__(256)
tri_kernel(const float* __restrict__ T,
           const float* __restrict__ K0,
           const float* __restrict__ K1,
           const float* __restrict__ mconf,
           const float* __restrict__ kp0,
           const float* __restrict__ kp1,
           float* __restrict__ out, int N) {
    int n = blockIdx.x * blockDim.x + threadIdx.x;
    if (n >= N) return;

    float2 p0 = reinterpret_cast<const float2*>(kp0)[n];
    float2 p1 = reinterpret_cast<const float2*>(kp1)[n];
    float  cf = mconf[n];

    // Projection matrices, per-thread (warp-uniform loads -> L1 broadcast;
    // ~36 FMAs = ~3% of thread work, cheaper than a dedicated prep launch).
    float P[24];
    // P0 = K0 @ [I|0]
#pragma unroll
    for (int r = 0; r < 3; r++) {
#pragma unroll
        for (int c = 0; c < 3; c++) P[r * 4 + c] = K0[r * 3 + c];
        P[r * 4 + 3] = 0.0f;
    }
    // P1 = K1 @ T[:3,:]
#pragma unroll
    for (int r = 0; r < 3; r++)
#pragma unroll
        for (int c = 0; c < 4; c++)
            P[12 + r * 4 + c] = fmaf(K1[r * 3 + 0], T[c],
                                fmaf(K1[r * 3 + 1], T[4 + c],
                                     K1[r * 3 + 2] * T[8 + c]));

    // A rows: (x0*P0r2 - P0r0), (y0*P0r2 - P0r1), cf*(x1*P1r2 - P1r0), cf*(y1*P1r2 - P1r1)
    float A[4][4];
#pragma unroll
    for (int j = 0; j < 4; j++) {
        A[0][j] = fmaf(p0.x, P[8 + j],  -P[0 + j]);
        A[1][j] = fmaf(p0.y, P[8 + j],  -P[4 + j]);
        A[2][j] = cf * fmaf(p1.x, P[20 + j], -P[12 + j]);
        A[3][j] = cf * fmaf(p1.y, P[20 + j], -P[16 + j]);
    }

    // Right-singular-vector accumulator: only rows 2 and 3 of V are ever read.
    float V2[4] = {0.f, 0.f, 1.f, 0.f};
    float V3[4] = {0.f, 0.f, 0.f, 1.f};

    // One-sided cyclic Jacobi SVD: orthogonalize column pairs of A.
    const int PP[6] = {0, 0, 0, 1, 1, 2};
    const int QQ[6] = {1, 2, 3, 2, 3, 3};
#pragma unroll 1
    for (int sw = 0; sw < NSWEEPS; sw++) {
#pragma unroll
        for (int pi = 0; pi < 6; pi++) {
            const int p = PP[pi], q = QQ[pi];
            float al = 0.0f, be = 0.0f, ga = 0.0f;
#pragma unroll
            for (int k = 0; k < 4; k++) {
                al = fmaf(A[k][p], A[k][p], al);
                be = fmaf(A[k][q], A[k][q], be);
                ga = fmaf(A[k][p], A[k][q], ga);
            }
            // Rotation zeroing the Gram off-diagonal:
            //   u = be-al, w = 2*ga, (c,s) ∝ (|u| + sqrt(u^2+w^2), w*sgn(u)).
            // Approx rsqrt keeps (c,s) an exact SCALED rotation: a common column
            // scale factor, which cancels in the final v2/v3 ratio.
            float u  = be - al;
            float w  = ga + ga;
            float zz = fmaf(u, u, w * w);
            float h  = zz * rsqrt_approx(zz);               // sqrt(u^2+w^2) on MUFU
            float d  = fabsf(u) + h;
            float sr = w * copysignf(1.0f, u);
            float rn = rsqrt_approx(fmaf(d, d, sr * sr));   // MUFU
            bool  ok = zz > 0.0f;                           // degenerate pair guard
            float c  = ok ? d * rn  : 1.0f;
            float s  = ok ? sr * rn : 0.0f;
#pragma unroll
            for (int k = 0; k < 4; k++) {
                float ap = A[k][p], aq = A[k][q];
                A[k][p] = fmaf(c, ap, -s * aq);
                A[k][q] = fmaf(s, ap,  c * aq);
            }
            { float vp = V2[p], vq = V2[q];
              V2[p] = fmaf(c, vp, -s * vq);
              V2[q] = fmaf(s, vp,  c * vq); }
            { float vp = V3[p], vq = V3[q];
              V3[p] = fmaf(c, vp, -s * vq);
              V3[q] = fmaf(s, vp,  c * vq); }
        }
    }

    // Column with smallest norm == smallest right singular vector.
    float best = 3.4e38f, v2 = 0.f, v3 = 1.f;
#pragma unroll
    for (int j = 0; j < 4; j++) {
        float t = 0.0f;
#pragma unroll
        for (int k = 0; k < 4; k++) t = fmaf(A[k][j], A[k][j], t);
        if (t < best) { best = t; v2 = V2[j]; v3 = V3[j]; }
    }

    // Sign of v cancels in the division. Clip(+-1000), clip(0,30), strict filter.
    float zraw = v2 * rcp_nr(v3);
    float pc   = fminf(fmaxf(zraw, -1000.0f), 1000.0f);
    float zc   = fminf(fmaxf(pc, 0.0f), 30.0f);
    float val  = (zc > 0.0f && zc < 30.0f) ? zc : 0.0f;

    out[HW_IMG + n] = val;

    // Sparse-depth scatter, last-write-wins. Pack (index+1, value-bits): 64-bit
    // max orders by index (high word), winner's depth rides in the low word —
    // resolve needs no dependent gather.
    int xi = (int)p0.x;   // trunc toward zero == .astype(int32) for x>=0
    int yi = (int)p0.y;
    unsigned long long pk =
        ((unsigned long long)(unsigned)(n + 1) << 32) | (unsigned)__float_as_uint(val);
    atomicMax(&g_pack[yi * W_IMG + xi], pk);
}

// Pure streaming: coalesced 8B read -> 4B write, plus self-clean reset.
__global__ void __launch_bounds__(256)
resolve_kernel(float* __restrict__ out) {
    int i = blockIdx.x * blockDim.x + threadIdx.x;
    if (i < HW_IMG) {
        unsigned long long pk = g_pack[i];
        out[i] = __uint_as_float((unsigned)(pk & 0xFFFFFFFFu));  // empty -> bits 0 -> 0.0f
        if (pk) g_pack[i] = 0ull;   // restore zero invariant for next replay
    }
}

extern "C" void kernel_launch(void* const* d_in, const int* in_sizes, int n_in,
                              void* d_out, int out_size) {
    const float* T     = (const float*)d_in[0];  // [1,4,4]
    const float* K0    = (const float*)d_in[1];  // [1,3,3]
    const float* K1    = (const float*)d_in[2];  // [1,3,3]
    const float* mconf = (const float*)d_in[3];  // [N]
    const float* kp0   = (const float*)d_in[4];  // [N,2]
    const float* kp1   = (const float*)d_in[5];  // [N,2]
    // d_in[6] = image0 (fixed 480x640), d_in[7] = m_bids (all zero, single batch)
    int N = in_sizes[3];
    float* out = (float*)d_out;  // [HW_IMG depth | N kp3d_val]

    tri_kernel<<<(N + 255) / 256, 256>>>(T, K0, K1, mconf, kp0, kp1, out, N);
    resolve_kernel<<<(HW_IMG + 255) / 256, 256>>>(out);
}

// round 6
// speedup vs baseline: 1.4352x; 1.0054x over previous
#include <cuda_runtime.h>
#include <cuda_bf16.h>

#define W_IMG 640
#define H_IMG 480
#define HW_IMG (W_IMG * H_IMG)
#define NSWEEPS 4

// Per-pixel packed winner: high 32 = point index+1 (last-write-wins key), low 32 =
// float bits of that point's depth. 0 = empty. Zero-init at load; resolve_kernel
// restores zeros after reading (invariant across graph replays). 16B-aligned for
// vectorized resolve.
__device__ __align__(16) unsigned long long g_pack[HW_IMG];

// ---- packed f32x2 helpers (FFMA2: 2 fp32 FMAs per issue slot; PTX-only) ----
#define FMA2(d, a, b, c) \
    asm("fma.rn.f32x2 %0, %1, %2, %3;" : "=l"(d) : "l"(a), "l"(b), "l"(c))
#define MUL2(d, a, b) \
    asm("mul.rn.f32x2 %0, %1, %2;" : "=l"(d) : "l"(a), "l"(b))

__device__ __forceinline__ unsigned long long pack2(float lo, float hi) {
    unsigned long long d;
    asm("mov.b64 %0, {%1, %2};" : "=l"(d)
        : "r"(__float_as_uint(lo)), "r"(__float_as_uint(hi)));
    return d;
}
__device__ __forceinline__ void unpack2(unsigned long long s, float& lo, float& hi) {
    unsigned int a, b;
    asm("mov.b64 {%0, %1}, %2;" : "=r"(a), "=r"(b) : "l"(s));
    lo = __uint_as_float(a);
    hi = __uint_as_float(b);
}

// MUFU.RSQ — keep rsqrt off the (bottleneck) FMA pipe.
__device__ __forceinline__ float rsqrt_approx(float x) {
    float y;
    asm("rsqrt.approx.f32 %0, %1;" : "=f"(y) : "f"(x));
    return y;
}
// rcp.approx + 1 Newton step: ~full fp32, used once per thread.
__device__ __forceinline__ float rcp_nr(float x) {
    float y;
    asm("rcp.approx.f32 %0, %1;" : "=f"(y) : "f"(x));
    return y * fmaf(-x, y, 2.0f);
}

__global__ void __launch_bounds__(256)
tri_kernel(const float* __restrict__ T,
           const float* __restrict__ K0,
           const float* __restrict__ K1,
           const float* __restrict__ mconf,
           const float* __restrict__ kp0,
           const float* __restrict__ kp1,
           float* __restrict__ out, int N) {
    int n = blockIdx.x * blockDim.x + threadIdx.x;
    if (n >= N) return;

    float2 p0 = reinterpret_cast<const float2*>(kp0)[n];
    float2 p1 = reinterpret_cast<const float2*>(kp1)[n];
    float  cf = mconf[n];

    // Projection matrices per-thread (warp-uniform loads -> L1 broadcast).
    float P[24];
#pragma unroll
    for (int r = 0; r < 3; r++) {
#pragma unroll
        for (int c = 0; c < 3; c++) P[r * 4 + c] = K0[r * 3 + c];
        P[r * 4 + 3] = 0.0f;
    }
#pragma unroll
    for (int r = 0; r < 3; r++)
#pragma unroll
        for (int c = 0; c < 4; c++)
            P[12 + r * 4 + c] = fmaf(K1[r * 3 + 0], T[c],
                                fmaf(K1[r * 3 + 1], T[4 + c],
                                     K1[r * 3 + 2] * T[8 + c]));

    // A packed by row pairs: A2[0][j] = (A[0][j], A[1][j]); A2[1][j] = (A[2][j], A[3][j]).
    unsigned long long A2[2][4];
#pragma unroll
    for (int j = 0; j < 4; j++) {
        float a0 = fmaf(p0.x, P[8 + j],  -P[0 + j]);
        float a1 = fmaf(p0.y, P[8 + j],  -P[4 + j]);
        float a2 = cf * fmaf(p1.x, P[20 + j], -P[12 + j]);
        float a3 = cf * fmaf(p1.y, P[20 + j], -P[16 + j]);
        A2[0][j] = pack2(a0, a1);
        A2[1][j] = pack2(a2, a3);
    }

    // V rows 2 & 3 packed together: VP[j] = (V2[j], V3[j]). Rotations mix V
    // columns within each row independently -> identical update for both lanes.
    unsigned long long VP[4] = { pack2(0.f, 0.f), pack2(0.f, 0.f),
                                 pack2(1.f, 0.f), pack2(0.f, 1.f) };

    const unsigned long long Z2 = 0ull;  // (0.0f, 0.0f)

    // One-sided cyclic Jacobi SVD on column pairs of A.
    const int PP[6] = {0, 0, 0, 1, 1, 2};
    const int QQ[6] = {1, 2, 3, 2, 3, 3};
#pragma unroll 1
    for (int sw = 0; sw < NSWEEPS; sw++) {
#pragma unroll
        for (int pi = 0; pi < 6; pi++) {
            const int p = PP[pi], q = QQ[pi];

            // Gram entries, 2-wide accumulate + horizontal add.
            unsigned long long al2 = Z2, be2 = Z2, ga2 = Z2;
#pragma unroll
            for (int h = 0; h < 2; h++) {
                FMA2(al2, A2[h][p], A2[h][p], al2);
                FMA2(be2, A2[h][q], A2[h][q], be2);
                FMA2(ga2, A2[h][p], A2[h][q], ga2);
            }
            float alo, ahi, blo, bhi, glo, ghi;
            unpack2(al2, alo, ahi);
            unpack2(be2, blo, bhi);
            unpack2(ga2, glo, ghi);
            float al = alo + ahi, be = blo + bhi, ga = glo + ghi;

            // Rotation zeroing the Gram off-diagonal:
            //   u = be-al, w = 2*ga, (c,s) ∝ (|u| + sqrt(u^2+w^2), w*sgn(u)).
            float u  = be - al;
            float w  = ga + ga;
            float zz = fmaf(u, u, w * w);
            float h_ = zz * rsqrt_approx(zz);               // sqrt(u^2+w^2), MUFU
            float d  = fabsf(u) + h_;
            // sr = w * sgn(u) via sign-bit xor (ALU pipe, not FMA)
            float sr = __uint_as_float(__float_as_uint(w) ^
                                       (__float_as_uint(u) & 0x80000000u));
            float rn = rsqrt_approx(fmaf(d, d, sr * sr));   // MUFU
            bool  ok = zz > 0.0f;                           // degenerate pair guard
            float c  = ok ? d * rn  : 1.0f;
            float s  = ok ? sr * rn : 0.0f;

            unsigned long long c2  = pack2(c, c);
            unsigned long long s2  = pack2(s, s);
            unsigned long long ns2 = pack2(-s, -s);

            // Column rotation, packed: 8 FFMA2-class ops for A, 4 for V.
#pragma unroll
            for (int h = 0; h < 2; h++) {
                unsigned long long ap = A2[h][p], aq = A2[h][q], t;
                MUL2(t, ns2, aq); FMA2(A2[h][p], c2, ap, t);
                MUL2(t, s2,  ap); FMA2(A2[h][q], c2, aq, t);
            }
            {
                unsigned long long vp = VP[p], vq = VP[q], t;
                MUL2(t, ns2, vq); FMA2(VP[p], c2, vp, t);
                MUL2(t, s2,  vp); FMA2(VP[q], c2, vq, t);
            }
        }
    }

    // Column with smallest norm == smallest right singular vector.
    float best = 3.4e38f;
    unsigned long long bestvp = VP[0];
#pragma unroll
    for (int j = 0; j < 4; j++) {
        unsigned long long acc = Z2;
#pragma unroll
        for (int h = 0; h < 2; h++) FMA2(acc, A2[h][j], A2[h][j], acc);
        float lo, hi;
        unpack2(acc, lo, hi);
        float t = lo + hi;
        if (t < best) { best = t; bestvp = VP[j]; }
    }
    float v2, v3;
    unpack2(bestvp, v2, v3);

    // Sign cancels in the division. Clip(+-1000), clip(0,30), strict filter.
    float zraw = v2 * rcp_nr(v3);
    float pc   = fminf(fmaxf(zraw, -1000.0f), 1000.0f);
    float zc   = fminf(fmaxf(pc, 0.0f), 30.0f);
    float val  = (zc > 0.0f && zc < 30.0f) ? zc : 0.0f;

    out[HW_IMG + n] = val;

    // Sparse-depth scatter, last-write-wins: 64-bit max orders by index (high
    // word); the winner's depth rides in the low word.
    int xi = (int)p0.x;   // trunc toward zero == .astype(int32) for x>=0
    int yi = (int)p0.y;
    unsigned long long pk =
        ((unsigned long long)(unsigned)(n + 1) << 32) | (unsigned)__float_as_uint(val);
    atomicMax(&g_pack[yi * W_IMG + xi], pk);
}

// Streaming resolve: 4 pixels/thread (2x 16B loads, 1x 16B store) + packed reset.
__global__ void __launch_bounds__(256)
resolve_kernel(float* __restrict__ out) {
    int i4 = (blockIdx.x * blockDim.x + threadIdx.x) * 4;
    if (i4 < HW_IMG) {
        const ulonglong2* src = reinterpret_cast<const ulonglong2*>(g_pack + i4);
        ulonglong2 a = src[0];
        ulonglong2 b = src[1];
        float4 o;
        o.x = __uint_as_float((unsigned)(a.x & 0xFFFFFFFFu));
        o.y = __uint_as_float((unsigned)(a.y & 0xFFFFFFFFu));
        o.z = __uint_as_float((unsigned)(b.x & 0xFFFFFFFFu));
        o.w = __uint_as_float((unsigned)(b.y & 0xFFFFFFFFu));
        *reinterpret_cast<float4*>(out + i4) = o;
        ulonglong2* dst = reinterpret_cast<ulonglong2*>(g_pack + i4);
        dst[0] = make_ulonglong2(0ull, 0ull);   // restore zero invariant
        dst[1] = make_ulonglong2(0ull, 0ull);
    }
}

extern "C" void kernel_launch(void* const* d_in, const int* in_sizes, int n_in,
                              void* d_out, int out_size) {
    const float* T     = (const float*)d_in[0];  // [1,4,4]
    const float* K0    = (const float*)d_in[1];  // [1,3,3]
    const float* K1    = (const float*)d_in[2];  // [1,3,3]
    const float* mconf = (const float*)d_in[3];  // [N]
    const float* kp0   = (const float*)d_in[4];  // [N,2]
    const float* kp1   = (const float*)d_in[5];  // [N,2]
    // d_in[6] = image0 (fixed 480x640), d_in[7] = m_bids (all zero, single batch)
    int N = in_sizes[3];
    float* out = (float*)d_out;  // [HW_IMG depth | N kp3d_val]

    tri_kernel<<<(N + 255) / 256, 256>>>(T, K0, K1, mconf, kp0, kp1, out, N);
    resolve_kernel<<<(HW_IMG / 4 + 255) / 256, 256>>>(out);
}

// round 7
// speedup vs baseline: 1.9471x; 1.3566x over previous
#include <cuda_runtime.h>
#include <cuda_bf16.h>

#define W_IMG 640
#define H_IMG 480
#define HW_IMG (W_IMG * H_IMG)
#define NSWEEPS 3

// Per-pixel packed winner: high 32 = point index+1 (last-write-wins key), low 32 =
// float bits of that point's depth. 0 = empty. Zero-init at load; resolve_kernel
// restores zeros after reading (invariant across graph replays).
__device__ __align__(16) unsigned long long g_pack[HW_IMG];

// ---- packed f32x2 helpers ----
#define FMA2(d, a, b, c) \
    asm("fma.rn.f32x2 %0, %1, %2, %3;" : "=l"(d) : "l"(a), "l"(b), "l"(c))
#define MUL2(d, a, b) \
    asm("mul.rn.f32x2 %0, %1, %2;" : "=l"(d) : "l"(a), "l"(b))

__device__ __forceinline__ unsigned long long pack2(float lo, float hi) {
    unsigned long long d;
    asm("mov.b64 %0, {%1, %2};" : "=l"(d)
        : "r"(__float_as_uint(lo)), "r"(__float_as_uint(hi)));
    return d;
}
__device__ __forceinline__ void unpack2(unsigned long long s, float& lo, float& hi) {
    unsigned int a, b;
    asm("mov.b64 {%0, %1}, %2;" : "=r"(a), "=r"(b) : "l"(s));
    lo = __uint_as_float(a);
    hi = __uint_as_float(b);
}

// MUFU.RSQ — keep rsqrt off the FMA pipe.
__device__ __forceinline__ float rsqrt_approx(float x) {
    float y;
    asm("rsqrt.approx.f32 %0, %1;" : "=f"(y) : "f"(x));
    return y;
}
// rcp.approx + 1 Newton step: ~full fp32, used once per point.
__device__ __forceinline__ float rcp_nr(float x) {
    float y;
    asm("rcp.approx.f32 %0, %1;" : "=f"(y) : "f"(x));
    return y * fmaf(-x, y, 2.0f);
}

// Per-point Jacobi state: A packed by row pairs, V rows 2&3 packed together.
struct PtState {
    unsigned long long A2[2][4];
    unsigned long long VP[4];
};

__device__ __forceinline__ void init_state(PtState& S, const float* P,
                                           float2 p0, float2 p1, float cf) {
#pragma unroll
    for (int j = 0; j < 4; j++) {
        float a0 = fmaf(p0.x, P[8 + j],  -P[0 + j]);
        float a1 = fmaf(p0.y, P[8 + j],  -P[4 + j]);
        float a2 = cf * fmaf(p1.x, P[20 + j], -P[12 + j]);
        float a3 = cf * fmaf(p1.y, P[20 + j], -P[16 + j]);
        S.A2[0][j] = pack2(a0, a1);
        S.A2[1][j] = pack2(a2, a3);
    }
    S.VP[0] = pack2(0.f, 0.f);
    S.VP[1] = pack2(0.f, 0.f);
    S.VP[2] = pack2(1.f, 0.f);
    S.VP[3] = pack2(0.f, 1.f);
}

// One Jacobi rotation on column pair (p, q). p,q are compile-time after unroll.
__device__ __forceinline__ void jacobi_rot(PtState& S, int p, int q) {
    const unsigned long long Z2 = 0ull;
    unsigned long long al2 = Z2, be2 = Z2, ga2 = Z2;
#pragma unroll
    for (int h = 0; h < 2; h++) {
        FMA2(al2, S.A2[h][p], S.A2[h][p], al2);
        FMA2(be2, S.A2[h][q], S.A2[h][q], be2);
        FMA2(ga2, S.A2[h][p], S.A2[h][q], ga2);
    }
    float alo, ahi, blo, bhi, glo, ghi;
    unpack2(al2, alo, ahi);
    unpack2(be2, blo, bhi);
    unpack2(ga2, glo, ghi);
    float al = alo + ahi, be = blo + bhi, ga = glo + ghi;

    // u = be-al, w = 2*ga, (c,s) ∝ (|u| + sqrt(u^2+w^2), w*sgn(u)).
    // Approx rsqrt keeps (c,s) an exact SCALED rotation; the common column
    // scale cancels in the final v2/v3 ratio.
    float u  = be - al;
    float w  = ga + ga;
    float zz = fmaf(u, u, w * w);
    float h_ = zz * rsqrt_approx(zz);               // sqrt(u^2+w^2), MUFU
    float d  = fabsf(u) + h_;
    float sr = __uint_as_float(__float_as_uint(w) ^
                               (__float_as_uint(u) & 0x80000000u));
    float rn = rsqrt_approx(fmaf(d, d, sr * sr));   // MUFU
    bool  ok = zz > 0.0f;                           // degenerate pair guard
    float c  = ok ? d * rn  : 1.0f;
    float s  = ok ? sr * rn : 0.0f;

    unsigned long long c2  = pack2(c, c);
    unsigned long long s2  = pack2(s, s);
    unsigned long long ns2 = pack2(-s, -s);
#pragma unroll
    for (int h = 0; h < 2; h++) {
        unsigned long long ap = S.A2[h][p], aq = S.A2[h][q], t;
        MUL2(t, ns2, aq); FMA2(S.A2[h][p], c2, ap, t);
        MUL2(t, s2,  ap); FMA2(S.A2[h][q], c2, aq, t);
    }
    {
        unsigned long long vp = S.VP[p], vq = S.VP[q], t;
        MUL2(t, ns2, vq); FMA2(S.VP[p], c2, vp, t);
        MUL2(t, s2,  vp); FMA2(S.VP[q], c2, vq, t);
    }
}

// Smallest-norm column -> depth value after clips + strict (0,30) filter.
__device__ __forceinline__ float finalize(PtState& S) {
    const unsigned long long Z2 = 0ull;
    float best = 3.4e38f;
    unsigned long long bestvp = S.VP[0];
#pragma unroll
    for (int j = 0; j < 4; j++) {
        unsigned long long acc = Z2;
#pragma unroll
        for (int h = 0; h < 2; h++) FMA2(acc, S.A2[h][j], S.A2[h][j], acc);
        float lo, hi;
        unpack2(acc, lo, hi);
        float t = lo + hi;
        if (t < best) { best = t; bestvp = S.VP[j]; }
    }
    float v2, v3;
    unpack2(bestvp, v2, v3);
    float zraw = v2 * rcp_nr(v3);
    float pc   = fminf(fmaxf(zraw, -1000.0f), 1000.0f);
    float zc   = fminf(fmaxf(pc, 0.0f), 30.0f);
    return (zc > 0.0f && zc < 30.0f) ? zc : 0.0f;
}

// ILP=2: each thread runs two independent Jacobi chains; the two dependency
// chains interleave in the scheduler and hide each other's MUFU/FMA latency.
__global__ void __launch_bounds__(256)
tri_kernel(const float* __restrict__ T,
           const float* __restrict__ K0,
           const float* __restrict__ K1,
           const float* __restrict__ mconf,
           const float* __restrict__ kp0,
           const float* __restrict__ kp1,
           float* __restrict__ out, int N) {
    int t  = blockIdx.x * blockDim.x + threadIdx.x;
    int n0 = t * 2;
    if (n0 >= N) return;
    bool has1 = (n0 + 1) < N;

    // Wide loads: one float4 covers both points' keypoints.
    float4 k0pair, k1pair;
    float2 cfpair;
    if (has1) {
        k0pair = reinterpret_cast<const float4*>(kp0)[t];
        k1pair = reinterpret_cast<const float4*>(kp1)[t];
        cfpair = reinterpret_cast<const float2*>(mconf)[t];
    } else {
        float2 a = reinterpret_cast<const float2*>(kp0)[n0];
        float2 b = reinterpret_cast<const float2*>(kp1)[n0];
        k0pair = make_float4(a.x, a.y, a.x, a.y);
        k1pair = make_float4(b.x, b.y, b.x, b.y);
        cfpair = make_float2(mconf[n0], mconf[n0]);
    }
    float2 p0a = make_float2(k0pair.x, k0pair.y);
    float2 p0b = make_float2(k0pair.z, k0pair.w);
    float2 p1a = make_float2(k1pair.x, k1pair.y);
    float2 p1b = make_float2(k1pair.z, k1pair.w);

    // Projection matrices (warp-uniform loads -> L1 broadcast; dead after init).
    float P[24];
#pragma unroll
    for (int r = 0; r < 3; r++) {
#pragma unroll
        for (int c = 0; c < 3; c++) P[r * 4 + c] = K0[r * 3 + c];
        P[r * 4 + 3] = 0.0f;
    }
#pragma unroll
    for (int r = 0; r < 3; r++)
#pragma unroll
        for (int c = 0; c < 4; c++)
            P[12 + r * 4 + c] = fmaf(K1[r * 3 + 0], T[c],
                                fmaf(K1[r * 3 + 1], T[4 + c],
                                     K1[r * 3 + 2] * T[8 + c]));

    PtState Sa, Sb;
    init_state(Sa, P, p0a, p1a, cfpair.x);
    init_state(Sb, P, p0b, p1b, cfpair.y);

    const int PP[6] = {0, 0, 0, 1, 1, 2};
    const int QQ[6] = {1, 2, 3, 2, 3, 3};
#pragma unroll 1
    for (int sw = 0; sw < NSWEEPS; sw++) {
#pragma unroll
        for (int pi = 0; pi < 6; pi++) {
            jacobi_rot(Sa, PP[pi], QQ[pi]);   // two independent chains —
            jacobi_rot(Sb, PP[pi], QQ[pi]);   // scheduler interleaves them
        }
    }

    float va = finalize(Sa);
    float vb = finalize(Sb);

    if (has1) {
        reinterpret_cast<float2*>(out + HW_IMG)[t] = make_float2(va, vb);
    } else {
        out[HW_IMG + n0] = va;
    }

    // Sparse-depth scatter, last-write-wins via 64-bit max keyed on index.
    {
        int xi = (int)p0a.x, yi = (int)p0a.y;
        unsigned long long pk =
            ((unsigned long long)(unsigned)(n0 + 1) << 32) | (unsigned)__float_as_uint(va);
        atomicMax(&g_pack[yi * W_IMG + xi], pk);
    }
    if (has1) {
        int xi = (int)p0b.x, yi = (int)p0b.y;
        unsigned long long pk =
            ((unsigned long long)(unsigned)(n0 + 2) << 32) | (unsigned)__float_as_uint(vb);
        atomicMax(&g_pack[yi * W_IMG + xi], pk);
    }
}

// Streaming resolve: 2 pixels/thread (16B load, 8B store, 16B reset).
__global__ void __launch_bounds__(256)
resolve_kernel(float* __restrict__ out) {
    int i2 = (blockIdx.x * blockDim.x + threadIdx.x) * 2;
    if (i2 < HW_IMG) {
        ulonglong2 a = *reinterpret_cast<const ulonglong2*>(g_pack + i2);
        float2 o;
        o.x = __uint_as_float((unsigned)(a.x & 0xFFFFFFFFu));
        o.y = __uint_as_float((unsigned)(a.y & 0xFFFFFFFFu));
        *reinterpret_cast<float2*>(out + i2) = o;
        *reinterpret_cast<ulonglong2*>(g_pack + i2) = make_ulonglong2(0ull, 0ull);
    }
}

extern "C" void kernel_launch(void* const* d_in, const int* in_sizes, int n_in,
                              void* d_out, int out_size) {
    const float* T     = (const float*)d_in[0];  // [1,4,4]
    const float* K0    = (const float*)d_in[1];  // [1,3,3]
    const float* K1    = (const float*)d_in[2];  // [1,3,3]
    const float* mconf = (const float*)d_in[3];  // [N]
    const float* kp0   = (const float*)d_in[4];  // [N,2]
    const float* kp1   = (const float*)d_in[5];  // [N,2]
    // d_in[6] = image0 (fixed 480x640), d_in[7] = m_bids (all zero, single batch)
    int N = in_sizes[3];
    float* out = (float*)d_out;  // [HW_IMG depth | N kp3d_val]

    int threads = (N + 1) / 2;
    tri_kernel<<<(threads + 255) / 256, 256>>>(T, K0, K1, mconf, kp0, kp1, out, N);
    resolve_kernel<<<(HW_IMG / 2 + 255) / 256, 256>>>(out);
}